// round 1
// baseline (speedup 1.0000x reference)
#include <cuda_runtime.h>
#include <cuda_bf16.h>
#include <cstdint>

// LBP layer, fully fused:
//   gray = dot(rgb, [0.2989, 0.587, 0.114])
//   s(y,x) = #{ (dy,dx) in 3x3 : gray_zpad(y+dy-1, x+dx-1) >= gray(y,x) }   (s=0 outside image)
//   lbp(y,x) = sum_{(dy,dx)!=(0,0)} K[dy][dx] * s_zpad(y+dy-1, x+dx-1)
// Shapes fixed by the problem: N=32, H=W=512, C=3. Output [N,H,W,1] fp32.

#define TS   32              // output tile (square)
#define GDIM 36              // gray tile with halo 2 on each side
#define SDIM 34              // s tile with halo 1 on each side
#define NTHREADS 256

__global__ __launch_bounds__(NTHREADS) void lbp_fused_kernel(
    const float* __restrict__ in,   // [N, H, W, 3]
    float* __restrict__ out,        // [N, H, W, 1]
    int H, int W)
{
    __shared__ float g[GDIM][GDIM + 1];   // +1 pad: conflict-free rows
    __shared__ float s[SDIM][SDIM + 1];

    const int tid = threadIdx.x;
    const int bx = blockIdx.x;            // tile col
    const int by = blockIdx.y;            // tile row
    const int n  = blockIdx.z;            // batch

    const int gx0 = bx * TS - 2;          // global coord of g[0][0]
    const int gy0 = by * TS - 2;

    const float* __restrict__ base = in + (size_t)n * H * W * 3;

    // ---- Phase 1: RGB -> gray into smem, zero outside image ----
    #pragma unroll
    for (int idx = tid; idx < GDIM * GDIM; idx += NTHREADS) {
        const int r = idx / GDIM;
        const int c = idx - r * GDIM;
        const int gy = gy0 + r;
        const int gx = gx0 + c;
        float v = 0.0f;
        if ((unsigned)gy < (unsigned)H && (unsigned)gx < (unsigned)W) {
            const float* p = base + ((size_t)gy * W + gx) * 3;
            const float rr = __ldg(p + 0);
            const float gg = __ldg(p + 1);
            const float bb = __ldg(p + 2);
            v = 0.2989f * rr + 0.587f * gg + 0.114f * bb;
        }
        g[r][c] = v;
    }
    __syncthreads();

    // ---- Phase 2: neighbor-count stencil -> s (masked to 0 outside image) ----
    #pragma unroll
    for (int idx = tid; idx < SDIM * SDIM; idx += NTHREADS) {
        const int r = idx / SDIM;
        const int c = idx - r * SDIM;
        const int gy = gy0 + 1 + r;       // s[r][c] <-> global (gy, gx)
        const int gx = gx0 + 1 + c;
        float val = 0.0f;
        if ((unsigned)gy < (unsigned)H && (unsigned)gx < (unsigned)W) {
            const float ctr = g[r + 1][c + 1];
            float cnt = 0.0f;
            #pragma unroll
            for (int dy = 0; dy < 3; dy++) {
                #pragma unroll
                for (int dx = 0; dx < 3; dx++) {
                    cnt += (g[r + dy][c + dx] >= ctr) ? 1.0f : 0.0f;
                }
            }
            val = cnt;
        }
        s[r][c] = val;
    }
    __syncthreads();

    // ---- Phase 3: LBP-weighted stencil of s, coalesced stores ----
    const int tx = tid & 31;              // output column within tile
    const int ty = tid >> 5;              // row group
    const int gx = bx * TS + tx;
    float* __restrict__ obase = out + (size_t)n * H * W;

    #pragma unroll
    for (int i = 0; i < 4; i++) {
        const int r  = ty + i * 8;        // output row within tile, 0..31
        const int gy = by * TS + r;
        // s[r+dy][tx+dx] corresponds to s at global (gy-1+dy, gx-1+dx)
        float v =   1.0f * s[r    ][tx    ]
                +   2.0f * s[r    ][tx + 1]
                +   4.0f * s[r    ][tx + 2]
                + 128.0f * s[r + 1][tx    ]
                +   8.0f * s[r + 1][tx + 2]
                +  64.0f * s[r + 2][tx    ]
                +  32.0f * s[r + 2][tx + 1]
                +  16.0f * s[r + 2][tx + 2];
        obase[(size_t)gy * W + gx] = v;
    }
}

extern "C" void kernel_launch(void* const* d_in, const int* in_sizes, int n_in,
                              void* d_out, int out_size)
{
    const float* in = (const float*)d_in[0];
    float* out = (float*)d_out;

    // in_sizes[0] = N*H*W*3. Problem shape is fixed: 32 x 512 x 512 x 3.
    const int H = 512, W = 512;
    const int N = in_sizes[0] / (H * W * 3);

    dim3 grid(W / TS, H / TS, N);
    lbp_fused_kernel<<<grid, NTHREADS>>>(in, out, H, W);
}

// round 2
// speedup vs baseline: 1.3133x; 1.3133x over previous
#include <cuda_runtime.h>
#include <cuda_bf16.h>
#include <cstdint>

// LBP layer, fully fused, register-rolling stencils:
//   gray = dot(rgb, [0.2989, 0.587, 0.114])
//   s(y,x) = #{ (dy,dx) in 3x3 : gray_zpad(y+dy-1,x+dx-1) >= gray(y,x) }  (s=0 outside image)
//   lbp(y,x) = sum_{(dy,dx)!=(1,1)} K[dy][dx] * s_zpad(y+dy-1,x+dx-1)
// Fixed shapes: N=32, H=W=512, C=3. Output [N,H,W,1] fp32.

#define TS      32           // output tile (square)
#define GROWS   36           // gray tile rows (halo 2)
#define GCOLS   36
#define GSTRIDE 38           // even (float2 stores), conflict-benign
#define SROWS   34           // s tile rows (halo 1)
#define SSTRIDE 36
#define NTHREADS 256

__global__ __launch_bounds__(NTHREADS) void lbp_fused_kernel(
    const float* __restrict__ in,   // [N, H, W, 3]
    float* __restrict__ out,        // [N, H, W, 1]
    int H, int W)
{
    __shared__ __align__(16) float g[GROWS * GSTRIDE];
    __shared__ __align__(16) float s[SROWS * SSTRIDE];

    const int tid = threadIdx.x;
    const int bx = blockIdx.x;
    const int by = blockIdx.y;
    const int n  = blockIdx.z;

    const int gx0 = bx * TS - 2;          // global coord of g(0,0)
    const int gy0 = by * TS - 2;

    const float* __restrict__ base = in + (size_t)n * H * W * 3;

    // Interior block: whole gray tile (incl. halo 2) inside the image.
    const bool interior = (gx0 >= 0) && (gx0 + GCOLS <= W) &&
                          (gy0 >= 0) && (gy0 + GROWS <= H);

    // ================= Phase 1: RGB -> gray into smem =================
    if (interior) {
        // float2 pair loads: gx0 is even, so (gy*W+gx)*3 floats is 8B-aligned.
        #pragma unroll
        for (int idx = tid; idx < GROWS * (GCOLS / 2); idx += NTHREADS) {
            const int r  = idx / (GCOLS / 2);
            const int pc = idx - r * (GCOLS / 2);
            const int gy = gy0 + r;
            const int gx = gx0 + 2 * pc;
            const float2* p = (const float2*)(base + ((size_t)gy * W + gx) * 3);
            const float2 v0 = __ldg(p + 0);
            const float2 v1 = __ldg(p + 1);
            const float2 v2 = __ldg(p + 2);
            const float g0 = fmaf(0.2989f, v0.x, fmaf(0.587f, v0.y, 0.114f * v1.x));
            const float g1 = fmaf(0.2989f, v1.y, fmaf(0.587f, v2.x, 0.114f * v2.y));
            *(float2*)&g[r * GSTRIDE + 2 * pc] = make_float2(g0, g1);
        }
    } else {
        #pragma unroll
        for (int idx = tid; idx < GROWS * GCOLS; idx += NTHREADS) {
            const int r = idx / GCOLS;
            const int c = idx - r * GCOLS;
            const int gy = gy0 + r;
            const int gx = gx0 + c;
            float v = 0.0f;
            if ((unsigned)gy < (unsigned)H && (unsigned)gx < (unsigned)W) {
                const float* p = base + ((size_t)gy * W + gx) * 3;
                v = fmaf(0.2989f, __ldg(p), fmaf(0.587f, __ldg(p + 1), 0.114f * __ldg(p + 2)));
            }
            g[r * GSTRIDE + c] = v;
        }
    }
    __syncthreads();

    // ====== Phase 2: neighbor-count stencil -> s (register-rolled rows) ======
    // 34 columns x 7 row-chunks = 238 active threads; rows per chunk: 5,5,5,5,5,5,4.
    if (tid < 7 * 34) {
        const int col   = tid % 34;
        const int chunk = tid / 34;
        const int r0    = chunk * 5;
        const int nr    = (chunk == 6) ? 4 : 5;

        const float* gp = &g[r0 * GSTRIDE + col];
        float p0 = gp[0],           p1 = gp[1],           p2 = gp[2];
        float q0 = gp[GSTRIDE],     q1 = gp[GSTRIDE + 1], q2 = gp[GSTRIDE + 2];
        float* sp = &s[r0 * SSTRIDE + col];

        if (interior) {
            #pragma unroll
            for (int i = 0; i < 5; i++) {
                if (i >= nr) break;
                const float* t = gp + (i + 2) * GSTRIDE;
                const float t0 = t[0], t1 = t[1], t2 = t[2];
                const float c = q1;                 // center: g(r0+i+1, col+1)
                float cnt = 1.0f;                   // center compare always true
                cnt += (p0 >= c) ? 1.0f : 0.0f;
                cnt += (p1 >= c) ? 1.0f : 0.0f;
                cnt += (p2 >= c) ? 1.0f : 0.0f;
                cnt += (q0 >= c) ? 1.0f : 0.0f;
                cnt += (q2 >= c) ? 1.0f : 0.0f;
                cnt += (t0 >= c) ? 1.0f : 0.0f;
                cnt += (t1 >= c) ? 1.0f : 0.0f;
                cnt += (t2 >= c) ? 1.0f : 0.0f;
                sp[i * SSTRIDE] = cnt;
                p0 = q0; p1 = q1; p2 = q2;
                q0 = t0; q1 = t1; q2 = t2;
            }
        } else {
            #pragma unroll
            for (int i = 0; i < 5; i++) {
                if (i >= nr) break;
                const float* t = gp + (i + 2) * GSTRIDE;
                const float t0 = t[0], t1 = t[1], t2 = t[2];
                const float c = q1;
                float cnt = 1.0f;
                cnt += (p0 >= c) ? 1.0f : 0.0f;
                cnt += (p1 >= c) ? 1.0f : 0.0f;
                cnt += (p2 >= c) ? 1.0f : 0.0f;
                cnt += (q0 >= c) ? 1.0f : 0.0f;
                cnt += (q2 >= c) ? 1.0f : 0.0f;
                cnt += (t0 >= c) ? 1.0f : 0.0f;
                cnt += (t1 >= c) ? 1.0f : 0.0f;
                cnt += (t2 >= c) ? 1.0f : 0.0f;
                const int gy = gy0 + 1 + r0 + i;    // global coords of this s point
                const int gx = gx0 + 1 + col;
                const bool ok = (unsigned)gy < (unsigned)H && (unsigned)gx < (unsigned)W;
                sp[i * SSTRIDE] = ok ? cnt : 0.0f;  // reference zero-pads s
                p0 = q0; p1 = q1; p2 = q2;
                q0 = t0; q1 = t1; q2 = t2;
            }
        }
    }
    __syncthreads();

    // ====== Phase 3: LBP-weighted stencil of s (register-rolled rows) ======
    // 32 columns x 8 row-chunks = 256 threads, 4 rows each.
    {
        const int x     = tid & 31;
        const int chunk = tid >> 5;
        const int r0    = chunk * 4;

        const float* sp = &s[r0 * SSTRIDE + x];
        float a0 = sp[0],           a1 = sp[1],           a2 = sp[2];
        float b0 = sp[SSTRIDE],     b1 = sp[SSTRIDE + 1], b2 = sp[SSTRIDE + 2];

        float* __restrict__ ob = out + (size_t)n * H * W
                               + (size_t)(by * TS + r0) * W + bx * TS + x;
        #pragma unroll
        for (int i = 0; i < 4; i++) {
            const float* t = sp + (i + 2) * SSTRIDE;
            const float c0 = t[0], c1 = t[1], c2 = t[2];
            float v = a0;
            v = fmaf(2.0f,   a1, v);
            v = fmaf(4.0f,   a2, v);
            v = fmaf(128.0f, b0, v);
            v = fmaf(8.0f,   b2, v);
            v = fmaf(64.0f,  c0, v);
            v = fmaf(32.0f,  c1, v);
            v = fmaf(16.0f,  c2, v);
            ob[(size_t)i * W] = v;
            a0 = b0; a1 = b1; a2 = b2;
            b0 = c0; b1 = c1; b2 = c2;
        }
    }
}

extern "C" void kernel_launch(void* const* d_in, const int* in_sizes, int n_in,
                              void* d_out, int out_size)
{
    const float* in = (const float*)d_in[0];
    float* out = (float*)d_out;

    const int H = 512, W = 512;
    const int N = in_sizes[0] / (H * W * 3);

    dim3 grid(W / TS, H / TS, N);
    lbp_fused_kernel<<<grid, NTHREADS>>>(in, out, H, W);
}